// round 17
// baseline (speedup 1.0000x reference)
#include <cuda_runtime.h>
#include <cuda_fp16.h>

#define N_NODES 50000
#define N_EDGES 800000

// Scratch (device globals — no allocation allowed). hs buffers hold
// dinv[row]-prescaled GEMM outputs (fp16) — norm factorization.
__device__ __align__(16) __half g_h1h[N_NODES * 128];  // hs1 = dinv*x @ W1
__device__ __align__(16) __half g_a1h[N_NODES * 128];  // layer1 aggregated (pre-relu)
__device__ __align__(16) __half g_h2h[N_NODES * 64];   // hs2 = dinv*relu(a1) @ W2
__device__ float g_dinv[N_NODES];
__device__ int   g_cnt[N_NODES];
__device__ int   g_rowoff[N_NODES];
__device__ int   g_cursor[N_NODES];
__device__ int   g_col[N_EDGES];   // 4B CSR entry: src only (norm factored out)
__device__ int   g_total;
__device__ int   g_is64;

// Pack a float into both halves of a 64-bit reg (f32x2 broadcast)
__device__ __forceinline__ unsigned long long pack2(float v) {
    unsigned long long r;
    asm("mov.b64 %0, {%1, %1};" : "=l"(r) : "f"(v));
    return r;
}
__device__ __forceinline__ void unpack2(unsigned long long a, float& lo, float& hi) {
    asm("mov.b64 {%0, %1}, %2;" : "=f"(lo), "=f"(hi) : "l"(a));
}
#define FMA2(acc, x, w) asm("fma.rn.f32x2 %0, %1, %2, %0;" : "+l"(acc) : "l"(x), "l"(w))

// L2-only 16-byte load (8 halves)
__device__ __forceinline__ uint4 ldcg4(const uint4* p) {
    uint4 v;
    asm("ld.global.cg.v4.u32 {%0,%1,%2,%3}, [%4];"
        : "=r"(v.x), "=r"(v.y), "=r"(v.z), "=r"(v.w) : "l"(p));
    return v;
}
// 4 halves (as 2x u32) -> float4
__device__ __forceinline__ float4 h4_to_f4(unsigned a, unsigned b) {
    float2 lo = __half22float2(*(__half2*)&a);
    float2 hi = __half22float2(*(__half2*)&b);
    return make_float4(lo.x, lo.y, hi.x, hi.y);
}
__device__ __forceinline__ float4 h4u2_to_f4(uint2 r) { return h4_to_f4(r.x, r.y); }
// float4 -> 4 halves (as uint2)
__device__ __forceinline__ uint2 f4_to_h4(float4 v) {
    __half2 p0 = __float22half2_rn(make_float2(v.x, v.y));
    __half2 p1 = __float22half2_rn(make_float2(v.z, v.w));
    uint2 r;
    r.x = *(unsigned*)&p0;
    r.y = *(unsigned*)&p1;
    return r;
}

#define ROWADD(acc, v) \
    acc.x += v.x; acc.y += v.y; acc.z += v.z; acc.w += v.w

// ---------------------------------------------------------------------------
// Zero counters + global cursor (all blocks) + dtype detection (block 0 warp 0).
// ---------------------------------------------------------------------------
__global__ void zero_detect_kernel(const int* __restrict__ ei32) {
    int i = blockIdx.x * blockDim.x + threadIdx.x;
    if (i < N_NODES) g_cnt[i] = 0;
    if (i == 0) g_total = 0;
    if (blockIdx.x == 0 && threadIdx.x < 32) {
        int t = threadIdx.x;
        int nz = 0;
        for (int k = t; k < 2048; k += 32)
            if (ei32[2 * k + 1] != 0) nz = 1;
        #pragma unroll
        for (int o = 16; o; o >>= 1) nz |= __shfl_xor_sync(0xffffffffu, nz, o);
        if (t == 0) g_is64 = (nz == 0) ? 1 : 0;
    }
}

// Count only (reads just the dst half of the edge list).
__global__ void count_kernel(const void* __restrict__ ei) {
    int e = blockIdx.x * blockDim.x + threadIdx.x;
    if (e >= N_EDGES) return;
    int d;
    if (g_is64) d = (int)((const long long*)ei)[N_EDGES + e];
    else        d = ((const int*)ei)[N_EDGES + e];
    d = min(max(d, 0), N_NODES - 1);
    atomicAdd(&g_cnt[d], 1);
}

// ---------------------------------------------------------------------------
// Slot allocation: block-local inclusive scan + ONE atomicAdd per block.
// Also computes cursor=rowoff and dinv. Unordered offsets harmless.
// ---------------------------------------------------------------------------
__global__ void alloc_kernel() {
    __shared__ int s[256];
    __shared__ int base;
    int t = threadIdx.x;
    int i = blockIdx.x * 256 + t;
    int v = (i < N_NODES) ? g_cnt[i] : 0;
    s[t] = v;
    __syncthreads();
    #pragma unroll
    for (int off = 1; off < 256; off <<= 1) {
        int add = (t >= off) ? s[t - off] : 0;
        __syncthreads();
        s[t] += add;
        __syncthreads();
    }
    if (t == 255) base = atomicAdd(&g_total, s[255]);
    __syncthreads();
    if (i < N_NODES) {
        int ro = base + s[t] - v;
        g_rowoff[i] = ro;
        g_cursor[i] = ro;
        g_dinv[i] = rsqrtf((float)(v + 1));
    }
}

// Fill CSR slots with src only — re-decodes the (L2-warm) raw edge list.
__global__ void fill_kernel(const void* __restrict__ ei) {
    int e = blockIdx.x * blockDim.x + threadIdx.x;
    if (e >= N_EDGES) return;
    int s, d;
    if (g_is64) {
        const long long* p = (const long long*)ei;
        s = (int)p[e];
        d = (int)p[N_EDGES + e];
    } else {
        const int* p = (const int*)ei;
        s = p[e];
        d = p[N_EDGES + e];
    }
    s = min(max(s, 0), N_NODES - 1);
    d = min(max(d, 0), N_NODES - 1);
    int pos = atomicAdd(&g_cursor[d], 1);
    g_col[pos] = s;
}

// ---------------------------------------------------------------------------
// FFMA2 GEMM: tile M=64 rows, N=64 cols, K=128; output fp16, input rows
// PRESCALED by dinv[row]. LAYER2 also applies relu.
// ---------------------------------------------------------------------------
#define XD_STRIDE 130
#define GEMM_SMEM (64 * XD_STRIDE * 8 + 128 * 64 * 4)

template <int WSTRIDE, bool RELU, bool LAYER1>
__global__ void __launch_bounds__(256) gemm_kernel(const float* __restrict__ Xin,
                                                   const float* __restrict__ W) {
    extern __shared__ __align__(16) unsigned char smem_raw[];
    unsigned long long* Xd = (unsigned long long*)smem_raw;          // [64][130]
    float* Ws = (float*)(smem_raw + 64 * XD_STRIDE * 8);             // [128][64]

    __half* H = LAYER1 ? g_h1h : g_h2h;

    const int tid = threadIdx.x;
    const int rowBase = blockIdx.x * 64;
    const int colBase = blockIdx.y * 64;

    #pragma unroll
    for (int i = 0; i < 8; i++) {
        int idx = tid + i * 256;            // (row, k4): 64*32
        int row = idx >> 5, k4 = (idx & 31) * 4;
        int grow = min(rowBase + row, N_NODES - 1);
        float sc = g_dinv[grow];
        float4 v;
        if (LAYER1) {
            v = *(const float4*)(Xin + (size_t)grow * 128 + k4);
        } else {
            v = h4u2_to_f4(*(const uint2*)(g_a1h + (size_t)grow * 128 + k4));
        }
        if (RELU) {
            v.x = fmaxf(v.x, 0.f); v.y = fmaxf(v.y, 0.f);
            v.z = fmaxf(v.z, 0.f); v.w = fmaxf(v.w, 0.f);
        }
        v.x *= sc; v.y *= sc; v.z *= sc; v.w *= sc;
        unsigned long long* p = &Xd[row * XD_STRIDE + k4];
        ((ulonglong2*)p)[0] = make_ulonglong2(pack2(v.x), pack2(v.y));
        ((ulonglong2*)p)[1] = make_ulonglong2(pack2(v.z), pack2(v.w));
    }
    #pragma unroll
    for (int i = 0; i < 8; i++) {
        int idx = tid + i * 256;            // (k, c4): 128*16
        int k = idx >> 4, c4 = (idx & 15) * 4;
        *(float4*)&Ws[k * 64 + c4] = *(const float4*)(W + k * WSTRIDE + colBase + c4);
    }
    __syncthreads();

    const int ty = tid >> 4;
    const int tx = tid & 15;
    unsigned long long acc[4][2];
    #pragma unroll
    for (int r = 0; r < 4; r++) { acc[r][0] = 0ull; acc[r][1] = 0ull; }

    const unsigned long long* xb = &Xd[ty * 4 * XD_STRIDE];
    const float* wb = &Ws[tx * 4];

    #pragma unroll 4
    for (int k = 0; k < 128; k++) {
        ulonglong2 w2 = *(const ulonglong2*)(wb + k * 64);
        #pragma unroll
        for (int r = 0; r < 4; r++) {
            unsigned long long xp = xb[r * XD_STRIDE + k];
            FMA2(acc[r][0], xp, w2.x);
            FMA2(acc[r][1], xp, w2.y);
        }
    }

    #pragma unroll
    for (int r = 0; r < 4; r++) {
        int grow = rowBase + ty * 4 + r;
        if (grow < N_NODES) {
            float4 o;
            unpack2(acc[r][0], o.x, o.y);
            unpack2(acc[r][1], o.z, o.w);
            *(uint2*)&H[(size_t)grow * WSTRIDE + colBase + tx * 4] = f4_to_h4(o);
        }
    }
}

// ---------------------------------------------------------------------------
// Layer-1 aggregation: 2 nodes per warp, 16 lanes/node, 16B LDG.128 gathers.
//   a1[n] = dinv[n]*(hs1[n] + sum_s hs1[s]) + b1
// ---------------------------------------------------------------------------
__global__ void agg128_kernel(const float* __restrict__ b) {
    int w = (blockIdx.x * blockDim.x + threadIdx.x) >> 5;
    int lane = threadIdx.x & 31;
    int n = w * 2 + (lane >> 4);
    int l = lane & 15;                 // 16B chunk: halves 8l..8l+7
    if (n >= N_NODES) return;

    int beg = g_rowoff[n];
    int cnt = g_cnt[n];
    float din = g_dinv[n];

    uint4 r = ldcg4((const uint4*)(g_h1h + (size_t)n * 128) + l);  // self
    float4 accL = h4_to_f4(r.x, r.y);
    float4 accH = h4_to_f4(r.z, r.w);

    int i = 0;
    for (; i + 4 <= cnt; i += 4) {
        int c0 = __ldg(g_col + beg + i);
        int c1 = __ldg(g_col + beg + i + 1);
        int c2 = __ldg(g_col + beg + i + 2);
        int c3 = __ldg(g_col + beg + i + 3);
        uint4 r0 = ldcg4((const uint4*)(g_h1h + (size_t)c0 * 128) + l);
        uint4 r1 = ldcg4((const uint4*)(g_h1h + (size_t)c1 * 128) + l);
        uint4 r2 = ldcg4((const uint4*)(g_h1h + (size_t)c2 * 128) + l);
        uint4 r3 = ldcg4((const uint4*)(g_h1h + (size_t)c3 * 128) + l);
        float4 v;
        v = h4_to_f4(r0.x, r0.y); ROWADD(accL, v);
        v = h4_to_f4(r0.z, r0.w); ROWADD(accH, v);
        v = h4_to_f4(r1.x, r1.y); ROWADD(accL, v);
        v = h4_to_f4(r1.z, r1.w); ROWADD(accH, v);
        v = h4_to_f4(r2.x, r2.y); ROWADD(accL, v);
        v = h4_to_f4(r2.z, r2.w); ROWADD(accH, v);
        v = h4_to_f4(r3.x, r3.y); ROWADD(accL, v);
        v = h4_to_f4(r3.z, r3.w); ROWADD(accH, v);
    }
    for (; i < cnt; i++) {
        int c0 = __ldg(g_col + beg + i);
        uint4 r0 = ldcg4((const uint4*)(g_h1h + (size_t)c0 * 128) + l);
        float4 v;
        v = h4_to_f4(r0.x, r0.y); ROWADD(accL, v);
        v = h4_to_f4(r0.z, r0.w); ROWADD(accH, v);
    }

    float4 b0 = ((const float4*)b)[2 * l];
    float4 b1 = ((const float4*)b)[2 * l + 1];
    float4 oL, oH;
    oL.x = fmaf(accL.x, din, b0.x); oL.y = fmaf(accL.y, din, b0.y);
    oL.z = fmaf(accL.z, din, b0.z); oL.w = fmaf(accL.w, din, b0.w);
    oH.x = fmaf(accH.x, din, b1.x); oH.y = fmaf(accH.y, din, b1.y);
    oH.z = fmaf(accH.z, din, b1.z); oH.w = fmaf(accH.w, din, b1.w);

    uint2 pL = f4_to_h4(oL);
    uint2 pH = f4_to_h4(oH);
    uint4 st = make_uint4(pL.x, pL.y, pH.x, pH.y);
    ((uint4*)(g_a1h + (size_t)n * 128))[l] = st;
}

// ---------------------------------------------------------------------------
// Layer-2 aggregation: 4 nodes per warp, 8 lanes/node, 16B LDG.128 gathers.
// FUSED with log_softmax (width-8 reductions).
// ---------------------------------------------------------------------------
__global__ void agg64_softmax_kernel(const float* __restrict__ b,
                                     float* __restrict__ out) {
    int w = (blockIdx.x * blockDim.x + threadIdx.x) >> 5;
    int lane = threadIdx.x & 31;
    int n = w * 4 + (lane >> 3);
    int l = lane & 7;                  // 16B chunk: halves 8l..8l+7
    if (n >= N_NODES) return;

    int beg = g_rowoff[n];
    int cnt = g_cnt[n];
    float din = g_dinv[n];

    uint4 r = ldcg4((const uint4*)(g_h2h + (size_t)n * 64) + l);  // self
    float4 accL = h4_to_f4(r.x, r.y);
    float4 accH = h4_to_f4(r.z, r.w);

    int i = 0;
    for (; i + 4 <= cnt; i += 4) {
        int c0 = __ldg(g_col + beg + i);
        int c1 = __ldg(g_col + beg + i + 1);
        int c2 = __ldg(g_col + beg + i + 2);
        int c3 = __ldg(g_col + beg + i + 3);
        uint4 r0 = ldcg4((const uint4*)(g_h2h + (size_t)c0 * 64) + l);
        uint4 r1 = ldcg4((const uint4*)(g_h2h + (size_t)c1 * 64) + l);
        uint4 r2 = ldcg4((const uint4*)(g_h2h + (size_t)c2 * 64) + l);
        uint4 r3 = ldcg4((const uint4*)(g_h2h + (size_t)c3 * 64) + l);
        float4 v;
        v = h4_to_f4(r0.x, r0.y); ROWADD(accL, v);
        v = h4_to_f4(r0.z, r0.w); ROWADD(accH, v);
        v = h4_to_f4(r1.x, r1.y); ROWADD(accL, v);
        v = h4_to_f4(r1.z, r1.w); ROWADD(accH, v);
        v = h4_to_f4(r2.x, r2.y); ROWADD(accL, v);
        v = h4_to_f4(r2.z, r2.w); ROWADD(accH, v);
        v = h4_to_f4(r3.x, r3.y); ROWADD(accL, v);
        v = h4_to_f4(r3.z, r3.w); ROWADD(accH, v);
    }
    for (; i < cnt; i++) {
        int c0 = __ldg(g_col + beg + i);
        uint4 r0 = ldcg4((const uint4*)(g_h2h + (size_t)c0 * 64) + l);
        float4 v;
        v = h4_to_f4(r0.x, r0.y); ROWADD(accL, v);
        v = h4_to_f4(r0.z, r0.w); ROWADD(accH, v);
    }

    float4 b0 = ((const float4*)b)[2 * l];
    float4 b1 = ((const float4*)b)[2 * l + 1];
    accL.x = fmaf(accL.x, din, b0.x); accL.y = fmaf(accL.y, din, b0.y);
    accL.z = fmaf(accL.z, din, b0.z); accL.w = fmaf(accL.w, din, b0.w);
    accH.x = fmaf(accH.x, din, b1.x); accH.y = fmaf(accH.y, din, b1.y);
    accH.z = fmaf(accH.z, din, b1.z); accH.w = fmaf(accH.w, din, b1.w);

    // log_softmax over the 64 values of node n (8 lanes x 8 values)
    float m = fmaxf(fmaxf(fmaxf(accL.x, accL.y), fmaxf(accL.z, accL.w)),
                    fmaxf(fmaxf(accH.x, accH.y), fmaxf(accH.z, accH.w)));
    #pragma unroll
    for (int o = 4; o; o >>= 1) m = fmaxf(m, __shfl_xor_sync(0xffffffffu, m, o, 8));
    float s = expf(accL.x - m) + expf(accL.y - m) + expf(accL.z - m) + expf(accL.w - m)
            + expf(accH.x - m) + expf(accH.y - m) + expf(accH.z - m) + expf(accH.w - m);
    #pragma unroll
    for (int o = 4; o; o >>= 1) s += __shfl_xor_sync(0xffffffffu, s, o, 8);
    float ls = m + logf(s);

    float4 oL, oH;
    oL.x = accL.x - ls; oL.y = accL.y - ls; oL.z = accL.z - ls; oL.w = accL.w - ls;
    oH.x = accH.x - ls; oH.y = accH.y - ls; oH.z = accH.z - ls; oH.w = accH.w - ls;
    ((float4*)(out + (size_t)n * 64))[2 * l] = oL;
    ((float4*)(out + (size_t)n * 64))[2 * l + 1] = oH;
}

// ---------------------------------------------------------------------------
extern "C" void kernel_launch(void* const* d_in, const int* in_sizes, int n_in,
                              void* d_out, int out_size) {
    // Bind inputs by UNIQUE element count (ordering/dtype robust).
    const float* x = nullptr;
    const void* ei = nullptr;
    const float *W1 = nullptr, *b1 = nullptr, *W2 = nullptr, *b2 = nullptr;
    for (int i = 0; i < n_in; i++) {
        switch (in_sizes[i]) {
            case 6400000: x  = (const float*)d_in[i]; break;
            case 1600000: ei = d_in[i]; break;
            case 16384:   W1 = (const float*)d_in[i]; break;
            case 128:     b1 = (const float*)d_in[i]; break;
            case 8192:    W2 = (const float*)d_in[i]; break;
            case 64:      b2 = (const float*)d_in[i]; break;
        }
    }
    float* out = (float*)d_out;

    // One-time host-side resources (no device memory involved).
    static cudaStream_t side = nullptr;
    static cudaEvent_t evFork = nullptr, evJoin = nullptr;
    if (!side) {
        cudaStreamCreateWithFlags(&side, cudaStreamNonBlocking);
        cudaEventCreateWithFlags(&evFork, cudaEventDisableTiming);
        cudaEventCreateWithFlags(&evJoin, cudaEventDisableTiming);
        cudaFuncSetAttribute(gemm_kernel<128, false, true>,
                             cudaFuncAttributeMaxDynamicSharedMemorySize, GEMM_SMEM);
        cudaFuncSetAttribute(gemm_kernel<64, true, false>,
                             cudaFuncAttributeMaxDynamicSharedMemorySize, GEMM_SMEM);
    }

    const int NB = (N_NODES + 255) / 256;  // 196
    const int EB = (N_EDGES + 255) / 256;

    // Main stream: counts + dinv (gemm1 needs dinv for input prescale).
    zero_detect_kernel<<<NB, 256>>>((const int*)ei);
    count_kernel<<<EB, 256>>>(ei);
    alloc_kernel<<<NB, 256>>>();

    // Fork: fill on side stream, overlapped with gemm1 on main.
    cudaEventRecord(evFork, 0);
    cudaStreamWaitEvent(side, evFork, 0);
    fill_kernel<<<EB, 256, 0, side>>>(ei);
    cudaEventRecord(evJoin, side);

    gemm_kernel<128, false, true><<<dim3(782, 2), 256, GEMM_SMEM>>>(x, W1);

    // Join: agg128 needs both gemm1 (hs1) and the CSR.
    cudaStreamWaitEvent(0, evJoin, 0);
    agg128_kernel<<<3125, 256>>>(b1);  // 25000 warps, 2 nodes each

    gemm_kernel<64, true, false><<<dim3(782, 1), 256, GEMM_SMEM>>>(nullptr, W2);
    agg64_softmax_kernel<<<1563, 256>>>(b2, out);  // 12504 warps, 4 nodes each
}